// round 4
// baseline (speedup 1.0000x reference)
#include <cuda_runtime.h>
#include <math.h>
#include <stdint.h>

// ---------------- problem constants ----------------
#define BGR   128          // graphs
#define NPER0 512          // nodes per graph, layer 0
#define EPG   8192         // edges per graph
#define EE    (BGR*EPG)    // 1048576 total edges
#define N0    (BGR*NPER0)  // 65536
#define K1    410
#define K2    328
#define N1    (BGR*K1)     // 52480 (divisible by 64)
#define HF    128          // feature dim
#define DOUT  10
#define BN_EPS 1e-5f

typedef unsigned long long u64;

// ---------------- static device scratch ----------------
__device__ float g_bufA[(size_t)N0*HF];   // GCN agg output
__device__ float g_bufB[(size_t)N0*HF];   // X@W
__device__ float g_bufC[(size_t)N1*HF];   // hp1
__device__ float g_dinv[N0];
__device__ int   g_remap[N0];
__device__ int   g_rowbase[N0];
__device__ int   g_rowcnt[N0];
__device__ int   g_csrsrc[EE];
__device__ u64   g_Wp1[64*HF];
__device__ u64   g_Wp2[64*HF];
__device__ float g_pool[3*BGR*HF];

// ---------------- packed fp32x2 fma ----------------
__device__ __forceinline__ u64 ffma2(u64 a, u64 b, u64 c) {
    u64 d;
    asm("fma.rn.f32x2 %0, %1, %2, %3;" : "=l"(d) : "l"(a), "l"(b), "l"(c));
    return d;
}

// ---------------- pack both weight matrices ----------------
__global__ void k_packW2(const float* __restrict__ W1, const float* __restrict__ W2,
                         u64* __restrict__ Wp1, u64* __restrict__ Wp2) {
    int i = blockIdx.x * blockDim.x + threadIdx.x;
    const int n = 64 * HF;
    if (i >= 2 * n) return;
    const float* W = (i < n) ? W1 : W2;
    u64* Wp = (i < n) ? Wp1 : Wp2;
    int j = (i < n) ? i : i - n;
    int kp = j >> 7, c = j & 127;
    u64 lo = __float_as_uint(W[(2 * kp) * HF + c]);
    u64 hi = __float_as_uint(W[(2 * kp + 1) * HF + c]);
    Wp[j] = lo | (hi << 32);
}

// ---------------- CSR build per graph (+ optional remap fusion) ----------------
__global__ void k_csr(const int* __restrict__ src, const int* __restrict__ dst,
                      const int* __restrict__ remap, int nper,
                      int* __restrict__ row_base, int* __restrict__ row_cnt,
                      int* __restrict__ csr_src, float* __restrict__ dinv) {
    __shared__ int cnt[512];
    __shared__ int off[512];
    __shared__ int cur[512];
    int g = blockIdx.x, i = threadIdx.x;
    cnt[i] = 0; cur[i] = 0;
    __syncthreads();
    int ebase = g * EPG;
    for (int t = i; t < EPG; t += 512) {
        int s = src[ebase + t];
        int d = dst[ebase + t];
        if (remap) {
            s = remap[s];
            d = (s >= 0) ? remap[d] : -1;
            if (d < 0) continue;
        }
        atomicAdd(&cnt[d - g * nper], 1);
    }
    __syncthreads();
    int c = cnt[i];
    off[i] = c;
    __syncthreads();
    for (int d = 1; d < 512; d <<= 1) {          // Hillis-Steele inclusive scan
        int t = (i >= d) ? off[i - d] : 0;
        __syncthreads();
        off[i] += t;
        __syncthreads();
    }
    int excl = off[i] - c;
    if (i < nper) {
        row_cnt[g * nper + i]  = c;
        row_base[g * nper + i] = ebase + excl;
        dinv[g * nper + i]     = rsqrtf(1.0f + (float)c);  // +1 self loop
    }
    __syncthreads();
    off[i] = excl;
    __syncthreads();
    for (int t = i; t < EPG; t += 512) {
        int s = src[ebase + t];
        int d = dst[ebase + t];
        if (remap) {
            s = remap[s];
            d = (s >= 0) ? remap[d] : -1;
            if (d < 0) continue;
        }
        int dl = d - g * nper;
        int p = atomicAdd(&cur[dl], 1);
        csr_src[ebase + off[dl] + p] = s;
    }
}

// ---------------- GEMM v3: Y[nrows,128] = X @ W, packed f32x2 ----------------
__global__ void __launch_bounds__(256, 2)
k_gemm3(const float* __restrict__ X, const u64* __restrict__ Wp,
        float* __restrict__ Y) {
    __shared__ float Xs[64][HF];
    int row0 = blockIdx.x * 64;
    int tid = threadIdx.x;
    #pragma unroll
    for (int j = 0; j < 8; j++) {
        int idx = j * 256 + tid;
        int r = idx >> 5, c4 = idx & 31;
        float4 v = *(const float4*)(X + (size_t)(row0 + r) * HF + c4 * 4);
        *(float4*)(&Xs[r][c4 * 4]) = v;
    }
    __syncthreads();
    int wid = tid >> 5, lane = tid & 31;
    int r0 = wid * 8, c0 = lane * 4;
    u64 acc[8][4] = {};
    const u64* wp = Wp + c0;
    #pragma unroll 1
    for (int kp4 = 0; kp4 < 16; kp4++) {
        const u64* wb = wp + (size_t)(kp4 * 4) * HF;
        ulonglong2 wA0 = *(const ulonglong2*)(wb);
        ulonglong2 wB0 = *(const ulonglong2*)(wb + 2);
        ulonglong2 wA1 = *(const ulonglong2*)(wb + HF);
        ulonglong2 wB1 = *(const ulonglong2*)(wb + HF + 2);
        ulonglong2 wA2 = *(const ulonglong2*)(wb + 2 * HF);
        ulonglong2 wB2 = *(const ulonglong2*)(wb + 2 * HF + 2);
        ulonglong2 wA3 = *(const ulonglong2*)(wb + 3 * HF);
        ulonglong2 wB3 = *(const ulonglong2*)(wb + 3 * HF + 2);
        #pragma unroll
        for (int i = 0; i < 8; i++) {
            ulonglong2 xa = *(const ulonglong2*)(&Xs[r0 + i][kp4 * 8]);
            ulonglong2 xb = *(const ulonglong2*)(&Xs[r0 + i][kp4 * 8 + 4]);
            acc[i][0] = ffma2(xa.x, wA0.x, acc[i][0]);
            acc[i][1] = ffma2(xa.x, wA0.y, acc[i][1]);
            acc[i][2] = ffma2(xa.x, wB0.x, acc[i][2]);
            acc[i][3] = ffma2(xa.x, wB0.y, acc[i][3]);
            acc[i][0] = ffma2(xa.y, wA1.x, acc[i][0]);
            acc[i][1] = ffma2(xa.y, wA1.y, acc[i][1]);
            acc[i][2] = ffma2(xa.y, wB1.x, acc[i][2]);
            acc[i][3] = ffma2(xa.y, wB1.y, acc[i][3]);
            acc[i][0] = ffma2(xb.x, wA2.x, acc[i][0]);
            acc[i][1] = ffma2(xb.x, wA2.y, acc[i][1]);
            acc[i][2] = ffma2(xb.x, wB2.x, acc[i][2]);
            acc[i][3] = ffma2(xb.x, wB2.y, acc[i][3]);
            acc[i][0] = ffma2(xb.y, wA3.x, acc[i][0]);
            acc[i][1] = ffma2(xb.y, wA3.y, acc[i][1]);
            acc[i][2] = ffma2(xb.y, wB3.x, acc[i][2]);
            acc[i][3] = ffma2(xb.y, wB3.y, acc[i][3]);
        }
    }
    #pragma unroll
    for (int i = 0; i < 8; i++) {
        int r = row0 + r0 + i;
        float2 p0 = *(float2*)&acc[i][0];
        float2 p1 = *(float2*)&acc[i][1];
        float2 p2 = *(float2*)&acc[i][2];
        float2 p3 = *(float2*)&acc[i][3];
        float4 o = make_float4(p0.x + p0.y, p1.x + p1.y, p2.x + p2.y, p3.x + p3.y);
        *(float4*)(Y + (size_t)r * HF + c0) = o;
    }
}

// ================= MEGA kernel: one CTA (512 thr) per graph =================
// smem-staged GCN aggregation (+bias, fused hs matvec), score aggregation,
// exact top-k, remap, tanh*BN*ReLU copy, fused pooled column sums.
__global__ void __launch_bounds__(512, 1)
k_mega(const float* __restrict__ H,
       const int* __restrict__ csr_src,
       const int* __restrict__ row_base, const int* __restrict__ row_cnt,
       const float* __restrict__ dinv,
       const float* __restrict__ bias, const float* __restrict__ sW,
       const float* __restrict__ sb,
       const float* __restrict__ bg, const float* __restrict__ bb,
       const float* __restrict__ bm, const float* __restrict__ bv,
       int nper, int k,
       float* __restrict__ outAgg, int* __restrict__ remap,
       float* __restrict__ hp /*may be null*/, float* __restrict__ pooled,
       int write_remap) {
    extern __shared__ float stage[];          // nper*64 floats (<=128 KB)
    __shared__ float di_s[512];
    __shared__ float hs_s[512];
    __shared__ float sc_s[512];
    __shared__ float tn_s[512];
    __shared__ int   keep[512];
    __shared__ int   inv_s[512];
    __shared__ float bnp[4][HF];
    __shared__ float pool_s[HF];

    int g = blockIdx.x, tid = threadIdx.x;
    int lane = tid & 31, wid = tid >> 5;
    int gbase = g * nper;

    if (tid < HF) {
        bnp[0][tid] = bg[tid]; bnp[1][tid] = bb[tid];
        bnp[2][tid] = bm[tid]; bnp[3][tid] = bv[tid];
        pool_s[tid] = 0.f;
    }
    di_s[tid] = (tid < nper) ? dinv[gbase + tid] : 0.f;
    hs_s[tid] = 0.f;
    __syncthreads();

    // ---- two feature-chunk passes of 64 ----
    #pragma unroll 1
    for (int cf = 0; cf < HF; cf += 64) {
        // stage dinv-scaled chunk: stage[row][0..63]
        for (int i2 = tid; i2 < nper * 16; i2 += 512) {
            int row = i2 >> 4, f4 = (i2 & 15) * 4;
            float4 v = *(const float4*)(H + (size_t)(gbase + row) * HF + cf + f4);
            float d = di_s[row];
            v.x *= d; v.y *= d; v.z *= d; v.w *= d;
            *(float4*)(&stage[row * 64 + f4]) = v;
        }
        __syncthreads();
        float b0 = bias[cf + lane], b1 = bias[cf + 32 + lane];
        float w0 = sW[cf + lane],   w1 = sW[cf + 32 + lane];
        for (int v = wid; v < nper; v += 16) {
            int base = row_base[gbase + v], cnt = row_cnt[gbase + v];
            float a0 = stage[v * 64 + lane];        // self term (pre-scaled)
            float a1 = stage[v * 64 + 32 + lane];
            int e = 0;
            for (; e + 2 <= cnt; e += 2) {
                int s0 = __ldg(&csr_src[base + e])     - gbase;
                int s1 = __ldg(&csr_src[base + e + 1]) - gbase;
                a0 += stage[s0 * 64 + lane]      + stage[s1 * 64 + lane];
                a1 += stage[s0 * 64 + 32 + lane] + stage[s1 * 64 + 32 + lane];
            }
            if (e < cnt) {
                int s0 = __ldg(&csr_src[base + e]) - gbase;
                a0 += stage[s0 * 64 + lane];
                a1 += stage[s0 * 64 + 32 + lane];
            }
            float d = di_s[v];
            float o0 = a0 * d + b0;
            float o1 = a1 * d + b1;
            outAgg[(size_t)(gbase + v) * HF + cf + lane]      = o0;
            outAgg[(size_t)(gbase + v) * HF + cf + 32 + lane] = o1;
            float p = o0 * w0 + o1 * w1;
            #pragma unroll
            for (int off = 16; off > 0; off >>= 1) p += __shfl_down_sync(0xFFFFFFFFu, p, off);
            if (lane == 0) hs_s[v] += p;
        }
        __syncthreads();
    }

    // ---- score aggregation (hs, dinv in smem) ----
    float scv = -1e30f;
    if (tid < nper) {
        int base = row_base[gbase + tid], cnt = row_cnt[gbase + tid];
        float acc = 0.f;
        int e = 0;
        for (; e + 2 <= cnt; e += 2) {
            int s0 = __ldg(&csr_src[base + e])     - gbase;
            int s1 = __ldg(&csr_src[base + e + 1]) - gbase;
            acc += hs_s[s0] * di_s[s0] + hs_s[s1] * di_s[s1];
        }
        if (e < cnt) {
            int s0 = __ldg(&csr_src[base + e]) - gbase;
            acc += hs_s[s0] * di_s[s0];
        }
        float di = di_s[tid];
        scv = acc * di + hs_s[tid] * di * di + sb[0];
    }
    sc_s[tid] = scv;
    __syncthreads();

    // ---- exact rank (ties -> lower index) ----
    int kept = 0;
    if (tid < nper) {
        float si = scv;
        int rank = 0;
        for (int j = 0; j < nper; j++) {
            float sj = sc_s[j];
            rank += (sj > si) || (sj == si && j < tid);
        }
        kept = (rank < k) ? 1 : 0;
    }
    keep[tid] = kept;
    __syncthreads();
    for (int d = 1; d < 512; d <<= 1) {          // inclusive scan
        int t = (tid >= d) ? keep[tid - d] : 0;
        __syncthreads();
        keep[tid] += t;
        __syncthreads();
    }
    if (tid < nper) {
        int pos = keep[tid] - 1;
        if (write_remap) remap[gbase + tid] = kept ? (g * k + pos) : -1;
        if (kept) {
            inv_s[pos] = tid;
            tn_s[pos]  = tanhf(sc_s[tid]);
        }
    }
    __syncthreads();

    // ---- copy kept rows: tanh gate + BN + ReLU; fused pooled column sums ----
    {
        int fg = tid & 31;          // feature group (constant per thread)
        int c4 = fg * 4;
        float g0 = bnp[0][c4+0], g1 = bnp[0][c4+1], g2 = bnp[0][c4+2], g3 = bnp[0][c4+3];
        float e0 = bnp[1][c4+0], e1 = bnp[1][c4+1], e2 = bnp[1][c4+2], e3 = bnp[1][c4+3];
        float m0 = bnp[2][c4+0], m1 = bnp[2][c4+1], m2 = bnp[2][c4+2], m3 = bnp[2][c4+3];
        float r0 = rsqrtf(bnp[3][c4+0] + BN_EPS), r1 = rsqrtf(bnp[3][c4+1] + BN_EPS);
        float r2 = rsqrtf(bnp[3][c4+2] + BN_EPS), r3 = rsqrtf(bnp[3][c4+3] + BN_EPS);
        float s0 = 0.f, s1 = 0.f, s2 = 0.f, s3 = 0.f;
        const float* abase = outAgg + (size_t)gbase * HF;
        float* obase = hp ? (hp + (size_t)g * k * HF) : (float*)0;
        for (int rn = tid >> 5; rn < k; rn += 16) {
            int ro = inv_s[rn];
            float t = tn_s[rn];
            float4 h = *(const float4*)(abase + (size_t)ro * HF + c4);
            float4 o;
            o.x = fmaxf(g0 * (h.x * t - m0) * r0 + e0, 0.f);
            o.y = fmaxf(g1 * (h.y * t - m1) * r1 + e1, 0.f);
            o.z = fmaxf(g2 * (h.z * t - m2) * r2 + e2, 0.f);
            o.w = fmaxf(g3 * (h.w * t - m3) * r3 + e3, 0.f);
            if (obase) *(float4*)(obase + (size_t)rn * HF + c4) = o;
            s0 += o.x; s1 += o.y; s2 += o.z; s3 += o.w;
        }
        atomicAdd(&pool_s[c4+0], s0);
        atomicAdd(&pool_s[c4+1], s1);
        atomicAdd(&pool_s[c4+2], s2);
        atomicAdd(&pool_s[c4+3], s3);
    }
    __syncthreads();
    if (tid < HF) pooled[g * HF + tid] = pool_s[tid];
}

// ---------------- per-graph feature sum of x (layer 0 pooled) ----------------
__global__ void k_pooled(const float* __restrict__ X, int nper, float* __restrict__ P) {
    __shared__ float red[4][HF];
    int g = blockIdx.x;
    int f = threadIdx.x & 127, q = threadIdx.x >> 7;
    const float* base = X + (size_t)g * nper * HF + f;
    float acc = 0.f;
    for (int r = q; r < nper; r += 4) acc += base[(size_t)r * HF];
    red[q][f] = acc;
    __syncthreads();
    if (q == 0)
        P[g * HF + f] = red[0][f] + red[1][f] + red[2][f] + red[3][f];
}

// ---------------- readout ----------------
__global__ void k_final(const float* __restrict__ P,
                        const float* __restrict__ W0, const float* __restrict__ b0,
                        const float* __restrict__ W1, const float* __restrict__ b1,
                        const float* __restrict__ W2, const float* __restrict__ b2,
                        float* __restrict__ out) {
    int idx = blockIdx.x * blockDim.x + threadIdx.x;
    if (idx >= BGR * DOUT) return;
    int b = idx / DOUT, o = idx % DOUT;
    float acc = b0[o] + b1[o] + b2[o];
    const float* p0 = P + b * HF;
    const float* p1 = P + (BGR + b) * HF;
    const float* p2 = P + (2 * BGR + b) * HF;
    const float* w0 = W0 + o * HF;
    const float* w1 = W1 + o * HF;
    const float* w2 = W2 + o * HF;
    #pragma unroll 4
    for (int f = 0; f < HF; f++)
        acc += p0[f] * w0[f] + p1[f] * w1[f] + p2[f] * w2[f];
    out[idx] = acc;
}

// ---------------- host launch ----------------
extern "C" void kernel_launch(void* const* d_in, const int* in_sizes, int n_in,
                              void* d_out, int out_size) {
    const float* x        = (const float*)d_in[0];
    const int*   ei       = (const int*)  d_in[1];
    const float* conv1_W  = (const float*)d_in[2];
    const float* conv1_b  = (const float*)d_in[3];
    const float* conv2_W  = (const float*)d_in[4];
    const float* conv2_b  = (const float*)d_in[5];
    const float* score1_W = (const float*)d_in[6];
    const float* score1_b = (const float*)d_in[7];
    const float* score2_W = (const float*)d_in[8];
    const float* score2_b = (const float*)d_in[9];
    const float* bn1_g    = (const float*)d_in[10];
    const float* bn1_b    = (const float*)d_in[11];
    const float* bn1_m    = (const float*)d_in[12];
    const float* bn1_v    = (const float*)d_in[13];
    const float* bn2_g    = (const float*)d_in[14];
    const float* bn2_b    = (const float*)d_in[15];
    const float* bn2_m    = (const float*)d_in[16];
    const float* bn2_v    = (const float*)d_in[17];
    const float* lin0_W   = (const float*)d_in[18];
    const float* lin0_b   = (const float*)d_in[19];
    const float* lin1_W   = (const float*)d_in[20];
    const float* lin1_b   = (const float*)d_in[21];
    const float* lin2_W   = (const float*)d_in[22];
    const float* lin2_b   = (const float*)d_in[23];
    float* out = (float*)d_out;

    const int* src0 = ei;
    const int* dst0 = ei + EE;

    float *bufA, *bufB, *bufC, *dinv, *pool;
    int *remap, *rowbase, *rowcnt, *csrsrc;
    u64 *wp1, *wp2;
    cudaGetSymbolAddress((void**)&bufA,   g_bufA);
    cudaGetSymbolAddress((void**)&bufB,   g_bufB);
    cudaGetSymbolAddress((void**)&bufC,   g_bufC);
    cudaGetSymbolAddress((void**)&dinv,   g_dinv);
    cudaGetSymbolAddress((void**)&remap,  g_remap);
    cudaGetSymbolAddress((void**)&rowbase,g_rowbase);
    cudaGetSymbolAddress((void**)&rowcnt, g_rowcnt);
    cudaGetSymbolAddress((void**)&csrsrc, g_csrsrc);
    cudaGetSymbolAddress((void**)&wp1,    g_Wp1);
    cudaGetSymbolAddress((void**)&wp2,    g_Wp2);
    cudaGetSymbolAddress((void**)&pool,   g_pool);

    const int MEGA_SMEM = 512 * 64 * (int)sizeof(float);   // 128 KB dynamic
    cudaFuncSetAttribute(k_mega, cudaFuncAttributeMaxDynamicSharedMemorySize, MEGA_SMEM);

    k_packW2<<<(2 * 64 * HF + 255) / 256, 256>>>(conv1_W, conv2_W, wp1, wp2);

    // ---------- layer 0 ----------
    k_csr<<<BGR, 512>>>(src0, dst0, nullptr, NPER0, rowbase, rowcnt, csrsrc, dinv);
    k_gemm3<<<N0 / 64, 256>>>(x, wp1, bufB);
    k_mega<<<BGR, 512, MEGA_SMEM>>>(bufB, csrsrc, rowbase, rowcnt, dinv,
                                    conv1_b, score1_W, score1_b,
                                    bn1_g, bn1_b, bn1_m, bn1_v,
                                    NPER0, K1, bufA, remap, bufC,
                                    pool + BGR * HF, 1);

    // ---------- layer 1 ----------
    k_csr<<<BGR, 512>>>(src0, dst0, remap, K1, rowbase, rowcnt, csrsrc, dinv);
    k_gemm3<<<N1 / 64, 256>>>(bufC, wp2, bufB);
    k_mega<<<BGR, 512, MEGA_SMEM>>>(bufB, csrsrc, rowbase, rowcnt, dinv,
                                    conv2_b, score2_W, score2_b,
                                    bn2_g, bn2_b, bn2_m, bn2_v,
                                    K1, K2, bufA, remap, nullptr,
                                    pool + 2 * BGR * HF, 0);

    // ---------- readout ----------
    k_pooled<<<BGR, 512>>>(x, NPER0, pool);
    k_final<<<(BGR * DOUT + 255) / 256, 256>>>(pool,
                                               lin0_W, lin0_b, lin1_W, lin1_b, lin2_W, lin2_b,
                                               out);
}

// round 5
// speedup vs baseline: 1.0954x; 1.0954x over previous
#include <cuda_runtime.h>
#include <math.h>
#include <stdint.h>

// ---------------- problem constants ----------------
#define BGR   128          // graphs
#define NPER0 512          // nodes per graph, layer 0
#define EPG   8192         // edges per graph
#define EE    (BGR*EPG)    // 1048576 total edges
#define N0    (BGR*NPER0)  // 65536
#define K1    410
#define K2    328
#define N1    (BGR*K1)     // 52480 (divisible by 64)
#define HF    128          // feature dim
#define DOUT  10
#define BN_EPS 1e-5f

typedef unsigned long long u64;

// ---------------- static device scratch ----------------
__device__ float g_bufA[(size_t)N0*HF];   // GCN agg output
__device__ float g_bufB[(size_t)N0*HF];   // X@W
__device__ float g_bufC[(size_t)N1*HF];   // hp1
__device__ float g_dinv[N0];
__device__ int   g_remap[N0];
__device__ int   g_rowbase[N0];
__device__ int   g_rowcnt[N0];
__device__ int   g_csrsrc[EE];
__device__ u64   g_Wp1[64*HF];
__device__ u64   g_Wp2[64*HF];
__device__ float g_pool[3*BGR*HF];

// ---------------- packed fp32x2 fma ----------------
__device__ __forceinline__ u64 ffma2(u64 a, u64 b, u64 c) {
    u64 d;
    asm("fma.rn.f32x2 %0, %1, %2, %3;" : "=l"(d) : "l"(a), "l"(b), "l"(c));
    return d;
}

// ---------------- pack both weight matrices ----------------
__global__ void k_packW2(const float* __restrict__ W1, const float* __restrict__ W2,
                         u64* __restrict__ Wp1, u64* __restrict__ Wp2) {
    int i = blockIdx.x * blockDim.x + threadIdx.x;
    const int n = 64 * HF;
    if (i >= 2 * n) return;
    const float* W = (i < n) ? W1 : W2;
    u64* Wp = (i < n) ? Wp1 : Wp2;
    int j = (i < n) ? i : i - n;
    int kp = j >> 7, c = j & 127;
    u64 lo = __float_as_uint(W[(2 * kp) * HF + c]);
    u64 hi = __float_as_uint(W[(2 * kp + 1) * HF + c]);
    Wp[j] = lo | (hi << 32);
}

// ---------------- CSR build per graph (+ optional remap fusion) ----------------
__global__ void k_csr(const int* __restrict__ src, const int* __restrict__ dst,
                      const int* __restrict__ remap, int nper,
                      int* __restrict__ row_base, int* __restrict__ row_cnt,
                      int* __restrict__ csr_src, float* __restrict__ dinv) {
    __shared__ int cnt[512];
    __shared__ int off[512];
    __shared__ int cur[512];
    int g = blockIdx.x, i = threadIdx.x;
    cnt[i] = 0; cur[i] = 0;
    __syncthreads();
    int ebase = g * EPG;
    for (int t = i; t < EPG; t += 512) {
        int s = src[ebase + t];
        int d = dst[ebase + t];
        if (remap) {
            s = remap[s];
            d = (s >= 0) ? remap[d] : -1;
            if (d < 0) continue;
        }
        atomicAdd(&cnt[d - g * nper], 1);
    }
    __syncthreads();
    int c = cnt[i];
    off[i] = c;
    __syncthreads();
    for (int d = 1; d < 512; d <<= 1) {          // Hillis-Steele inclusive scan
        int t = (i >= d) ? off[i - d] : 0;
        __syncthreads();
        off[i] += t;
        __syncthreads();
    }
    int excl = off[i] - c;
    if (i < nper) {
        row_cnt[g * nper + i]  = c;
        row_base[g * nper + i] = ebase + excl;
        dinv[g * nper + i]     = rsqrtf(1.0f + (float)c);  // +1 self loop
    }
    __syncthreads();
    off[i] = excl;
    __syncthreads();
    for (int t = i; t < EPG; t += 512) {
        int s = src[ebase + t];
        int d = dst[ebase + t];
        if (remap) {
            s = remap[s];
            d = (s >= 0) ? remap[d] : -1;
            if (d < 0) continue;
        }
        int dl = d - g * nper;
        int p = atomicAdd(&cur[dl], 1);
        csr_src[ebase + off[dl] + p] = s;
    }
}

// ---------------- GEMM v3: Y[nrows,128] = X @ W, packed f32x2 ----------------
__global__ void __launch_bounds__(256, 2)
k_gemm3(const float* __restrict__ X, const u64* __restrict__ Wp,
        float* __restrict__ Y) {
    __shared__ float Xs[64][HF];
    int row0 = blockIdx.x * 64;
    int tid = threadIdx.x;
    #pragma unroll
    for (int j = 0; j < 8; j++) {
        int idx = j * 256 + tid;
        int r = idx >> 5, c4 = idx & 31;
        float4 v = *(const float4*)(X + (size_t)(row0 + r) * HF + c4 * 4);
        *(float4*)(&Xs[r][c4 * 4]) = v;
    }
    __syncthreads();
    int wid = tid >> 5, lane = tid & 31;
    int r0 = wid * 8, c0 = lane * 4;
    u64 acc[8][4] = {};
    const u64* wp = Wp + c0;
    #pragma unroll 1
    for (int kp4 = 0; kp4 < 16; kp4++) {
        const u64* wb = wp + (size_t)(kp4 * 4) * HF;
        ulonglong2 wA0 = *(const ulonglong2*)(wb);
        ulonglong2 wB0 = *(const ulonglong2*)(wb + 2);
        ulonglong2 wA1 = *(const ulonglong2*)(wb + HF);
        ulonglong2 wB1 = *(const ulonglong2*)(wb + HF + 2);
        ulonglong2 wA2 = *(const ulonglong2*)(wb + 2 * HF);
        ulonglong2 wB2 = *(const ulonglong2*)(wb + 2 * HF + 2);
        ulonglong2 wA3 = *(const ulonglong2*)(wb + 3 * HF);
        ulonglong2 wB3 = *(const ulonglong2*)(wb + 3 * HF + 2);
        #pragma unroll
        for (int i = 0; i < 8; i++) {
            ulonglong2 xa = *(const ulonglong2*)(&Xs[r0 + i][kp4 * 8]);
            ulonglong2 xb = *(const ulonglong2*)(&Xs[r0 + i][kp4 * 8 + 4]);
            acc[i][0] = ffma2(xa.x, wA0.x, acc[i][0]);
            acc[i][1] = ffma2(xa.x, wA0.y, acc[i][1]);
            acc[i][2] = ffma2(xa.x, wB0.x, acc[i][2]);
            acc[i][3] = ffma2(xa.x, wB0.y, acc[i][3]);
            acc[i][0] = ffma2(xa.y, wA1.x, acc[i][0]);
            acc[i][1] = ffma2(xa.y, wA1.y, acc[i][1]);
            acc[i][2] = ffma2(xa.y, wB1.x, acc[i][2]);
            acc[i][3] = ffma2(xa.y, wB1.y, acc[i][3]);
            acc[i][0] = ffma2(xb.x, wA2.x, acc[i][0]);
            acc[i][1] = ffma2(xb.x, wA2.y, acc[i][1]);
            acc[i][2] = ffma2(xb.x, wB2.x, acc[i][2]);
            acc[i][3] = ffma2(xb.x, wB2.y, acc[i][3]);
            acc[i][0] = ffma2(xb.y, wA3.x, acc[i][0]);
            acc[i][1] = ffma2(xb.y, wA3.y, acc[i][1]);
            acc[i][2] = ffma2(xb.y, wB3.x, acc[i][2]);
            acc[i][3] = ffma2(xb.y, wB3.y, acc[i][3]);
        }
    }
    #pragma unroll
    for (int i = 0; i < 8; i++) {
        int r = row0 + r0 + i;
        float2 p0 = *(float2*)&acc[i][0];
        float2 p1 = *(float2*)&acc[i][1];
        float2 p2 = *(float2*)&acc[i][2];
        float2 p3 = *(float2*)&acc[i][3];
        float4 o = make_float4(p0.x + p0.y, p1.x + p1.y, p2.x + p2.y, p3.x + p3.y);
        *(float4*)(Y + (size_t)r * HF + c0) = o;
    }
}

// ================= MEGA v2: one CTA (1024 thr) per graph =================
// Paired-feature lanes (LDS.64), 4-edge unroll, smem-staged aggregation,
// fused hs matvec, score agg, exact top-k, remap, tanh*BN*ReLU copy + pooled.
__global__ void __launch_bounds__(1024, 1)
k_mega(const float* __restrict__ H,
       const int* __restrict__ csr_src,
       const int* __restrict__ row_base, const int* __restrict__ row_cnt,
       const float* __restrict__ dinv,
       const float* __restrict__ bias, const float* __restrict__ sW,
       const float* __restrict__ sb,
       const float* __restrict__ bg, const float* __restrict__ bb,
       const float* __restrict__ bm, const float* __restrict__ bv,
       int nper, int k,
       float* __restrict__ outAgg, int* __restrict__ remap,
       float* __restrict__ hp /*may be null*/, float* __restrict__ pooled,
       int write_remap) {
    extern __shared__ float stage[];          // nper*64 floats (row-major chunk)
    __shared__ float di_s[512];
    __shared__ float hs_s[512];
    __shared__ float sc_s[512];
    __shared__ float tn_s[512];
    __shared__ int   keep[512];
    __shared__ int   inv_s[512];
    __shared__ float bnA[HF];      // g * rsqrt(v+eps)
    __shared__ float bnC[HF];      // b - A*m
    __shared__ float pool_s[HF];

    int g = blockIdx.x, tid = threadIdx.x;
    int lane = tid & 31, wid = tid >> 5;
    int gbase = g * nper;

    if (tid < HF) {
        float A = bg[tid] * rsqrtf(bv[tid] + BN_EPS);
        bnA[tid] = A;
        bnC[tid] = bb[tid] - A * bm[tid];
        pool_s[tid] = 0.f;
    }
    if (tid < 512) {
        di_s[tid] = (tid < nper) ? dinv[gbase + tid] : 0.f;
        hs_s[tid] = 0.f;
    }
    __syncthreads();

    // ---- two feature-chunk passes of 64 ----
    #pragma unroll 1
    for (int cf = 0; cf < HF; cf += 64) {
        // stage dinv-scaled chunk, row-major 64 floats per row
        for (int i2 = tid; i2 < nper * 16; i2 += 1024) {
            int row = i2 >> 4, f4 = (i2 & 15) * 4;
            float4 v = *(const float4*)(H + (size_t)(gbase + row) * HF + cf + f4);
            float d = di_s[row];
            v.x *= d; v.y *= d; v.z *= d; v.w *= d;
            *(float4*)(&stage[row * 64 + f4]) = v;
        }
        __syncthreads();
        // thread lane owns feature pair (2*lane, 2*lane+1) of this chunk
        int fp = 2 * lane;
        float2 bp = *(const float2*)(bias + cf + fp);
        float2 wp = *(const float2*)(sW + cf + fp);
        for (int v = wid; v < nper; v += 32) {
            int base = row_base[gbase + v], cnt = row_cnt[gbase + v];
            float2 self = *(const float2*)(&stage[v * 64 + fp]);   // pre-scaled
            float a0x = self.x, a0y = self.y;
            float a1x = 0.f, a1y = 0.f;
            int e = 0;
            for (; e + 4 <= cnt; e += 4) {
                int s0 = __ldg(&csr_src[base + e])     - gbase;
                int s1 = __ldg(&csr_src[base + e + 1]) - gbase;
                int s2 = __ldg(&csr_src[base + e + 2]) - gbase;
                int s3 = __ldg(&csr_src[base + e + 3]) - gbase;
                float2 v0 = *(const float2*)(&stage[s0 * 64 + fp]);
                float2 v1 = *(const float2*)(&stage[s1 * 64 + fp]);
                float2 v2 = *(const float2*)(&stage[s2 * 64 + fp]);
                float2 v3 = *(const float2*)(&stage[s3 * 64 + fp]);
                a0x += v0.x + v1.x; a0y += v0.y + v1.y;
                a1x += v2.x + v3.x; a1y += v2.y + v3.y;
            }
            for (; e < cnt; e++) {
                int s0 = __ldg(&csr_src[base + e]) - gbase;
                float2 v0 = *(const float2*)(&stage[s0 * 64 + fp]);
                a0x += v0.x; a0y += v0.y;
            }
            float d = di_s[v];
            float o0 = (a0x + a1x) * d + bp.x;
            float o1 = (a0y + a1y) * d + bp.y;
            *(float2*)(outAgg + (size_t)(gbase + v) * HF + cf + fp) = make_float2(o0, o1);
            float p = o0 * wp.x + o1 * wp.y;
            #pragma unroll
            for (int off = 16; off > 0; off >>= 1) p += __shfl_down_sync(0xFFFFFFFFu, p, off);
            if (lane == 0) hs_s[v] += p;
        }
        __syncthreads();
    }

    // ---- score aggregation (hs, dinv in smem) ----
    float scv = -1e30f;
    if (tid < nper) {
        int base = row_base[gbase + tid], cnt = row_cnt[gbase + tid];
        float acc0 = 0.f, acc1 = 0.f;
        int e = 0;
        for (; e + 4 <= cnt; e += 4) {
            int s0 = __ldg(&csr_src[base + e])     - gbase;
            int s1 = __ldg(&csr_src[base + e + 1]) - gbase;
            int s2 = __ldg(&csr_src[base + e + 2]) - gbase;
            int s3 = __ldg(&csr_src[base + e + 3]) - gbase;
            acc0 += hs_s[s0] * di_s[s0] + hs_s[s1] * di_s[s1];
            acc1 += hs_s[s2] * di_s[s2] + hs_s[s3] * di_s[s3];
        }
        for (; e < cnt; e++) {
            int s0 = __ldg(&csr_src[base + e]) - gbase;
            acc0 += hs_s[s0] * di_s[s0];
        }
        float di = di_s[tid];
        scv = (acc0 + acc1) * di + hs_s[tid] * di * di + sb[0];
    }
    if (tid < 512) sc_s[tid] = scv;
    __syncthreads();

    // ---- exact rank (ties -> lower index) ----
    int kept = 0;
    if (tid < nper) {
        float si = scv;
        int rank = 0;
        for (int j = 0; j < nper; j++) {
            float sj = sc_s[j];
            rank += (sj > si) || (sj == si && j < tid);
        }
        kept = (rank < k) ? 1 : 0;
    }
    if (tid < 512) keep[tid] = kept;
    __syncthreads();
    for (int d = 1; d < 512; d <<= 1) {          // inclusive scan over 512
        int t = 0;
        if (tid < 512 && tid >= d) t = keep[tid - d];
        __syncthreads();
        if (tid < 512) keep[tid] += t;
        __syncthreads();
    }
    if (tid < nper) {
        int pos = keep[tid] - 1;
        if (write_remap) remap[gbase + tid] = kept ? (g * k + pos) : -1;
        if (kept) {
            inv_s[pos] = tid;
            tn_s[pos]  = tanhf(sc_s[tid]);
        }
    }
    __syncthreads();

    // ---- copy kept rows: tanh gate + BN(folded) + ReLU; fused pooled sums ----
    {
        int c4 = (tid & 31) * 4;      // constant per thread (stride 1024 ≡ 0 mod 32)
        float A0 = bnA[c4+0], A1 = bnA[c4+1], A2 = bnA[c4+2], A3 = bnA[c4+3];
        float C0 = bnC[c4+0], C1 = bnC[c4+1], C2 = bnC[c4+2], C3 = bnC[c4+3];
        float s0 = 0.f, s1 = 0.f, s2 = 0.f, s3 = 0.f;
        const float* abase = outAgg + (size_t)gbase * HF;
        float* obase = hp ? (hp + (size_t)g * k * HF) : (float*)0;
        for (int rn = tid >> 5; rn < k; rn += 32) {
            int ro = inv_s[rn];
            float t = tn_s[rn];
            float4 h = *(const float4*)(abase + (size_t)ro * HF + c4);
            float4 o;
            o.x = fmaxf(A0 * (h.x * t) + C0, 0.f);
            o.y = fmaxf(A1 * (h.y * t) + C1, 0.f);
            o.z = fmaxf(A2 * (h.z * t) + C2, 0.f);
            o.w = fmaxf(A3 * (h.w * t) + C3, 0.f);
            if (obase) *(float4*)(obase + (size_t)rn * HF + c4) = o;
            s0 += o.x; s1 += o.y; s2 += o.z; s3 += o.w;
        }
        atomicAdd(&pool_s[c4+0], s0);
        atomicAdd(&pool_s[c4+1], s1);
        atomicAdd(&pool_s[c4+2], s2);
        atomicAdd(&pool_s[c4+3], s3);
    }
    __syncthreads();
    if (tid < HF) pooled[g * HF + tid] = pool_s[tid];
}

// ---------------- per-graph feature sum of x (layer 0 pooled) ----------------
__global__ void k_pooled(const float* __restrict__ X, int nper, float* __restrict__ P) {
    __shared__ float red[4][HF];
    int g = blockIdx.x;
    int f = threadIdx.x & 127, q = threadIdx.x >> 7;
    const float* base = X + (size_t)g * nper * HF + f;
    float acc = 0.f;
    for (int r = q; r < nper; r += 4) acc += base[(size_t)r * HF];
    red[q][f] = acc;
    __syncthreads();
    if (q == 0)
        P[g * HF + f] = red[0][f] + red[1][f] + red[2][f] + red[3][f];
}

// ---------------- readout ----------------
__global__ void k_final(const float* __restrict__ P,
                        const float* __restrict__ W0, const float* __restrict__ b0,
                        const float* __restrict__ W1, const float* __restrict__ b1,
                        const float* __restrict__ W2, const float* __restrict__ b2,
                        float* __restrict__ out) {
    int idx = blockIdx.x * blockDim.x + threadIdx.x;
    if (idx >= BGR * DOUT) return;
    int b = idx / DOUT, o = idx % DOUT;
    float acc = b0[o] + b1[o] + b2[o];
    const float* p0 = P + b * HF;
    const float* p1 = P + (BGR + b) * HF;
    const float* p2 = P + (2 * BGR + b) * HF;
    const float* w0 = W0 + o * HF;
    const float* w1 = W1 + o * HF;
    const float* w2 = W2 + o * HF;
    #pragma unroll 4
    for (int f = 0; f < HF; f++)
        acc += p0[f] * w0[f] + p1[f] * w1[f] + p2[f] * w2[f];
    out[idx] = acc;
}

// ---------------- host launch ----------------
extern "C" void kernel_launch(void* const* d_in, const int* in_sizes, int n_in,
                              void* d_out, int out_size) {
    const float* x        = (const float*)d_in[0];
    const int*   ei       = (const int*)  d_in[1];
    const float* conv1_W  = (const float*)d_in[2];
    const float* conv1_b  = (const float*)d_in[3];
    const float* conv2_W  = (const float*)d_in[4];
    const float* conv2_b  = (const float*)d_in[5];
    const float* score1_W = (const float*)d_in[6];
    const float* score1_b = (const float*)d_in[7];
    const float* score2_W = (const float*)d_in[8];
    const float* score2_b = (const float*)d_in[9];
    const float* bn1_g    = (const float*)d_in[10];
    const float* bn1_b    = (const float*)d_in[11];
    const float* bn1_m    = (const float*)d_in[12];
    const float* bn1_v    = (const float*)d_in[13];
    const float* bn2_g    = (const float*)d_in[14];
    const float* bn2_b    = (const float*)d_in[15];
    const float* bn2_m    = (const float*)d_in[16];
    const float* bn2_v    = (const float*)d_in[17];
    const float* lin0_W   = (const float*)d_in[18];
    const float* lin0_b   = (const float*)d_in[19];
    const float* lin1_W   = (const float*)d_in[20];
    const float* lin1_b   = (const float*)d_in[21];
    const float* lin2_W   = (const float*)d_in[22];
    const float* lin2_b   = (const float*)d_in[23];
    float* out = (float*)d_out;

    const int* src0 = ei;
    const int* dst0 = ei + EE;

    float *bufA, *bufB, *bufC, *dinv, *pool;
    int *remap, *rowbase, *rowcnt, *csrsrc;
    u64 *wp1, *wp2;
    cudaGetSymbolAddress((void**)&bufA,   g_bufA);
    cudaGetSymbolAddress((void**)&bufB,   g_bufB);
    cudaGetSymbolAddress((void**)&bufC,   g_bufC);
    cudaGetSymbolAddress((void**)&dinv,   g_dinv);
    cudaGetSymbolAddress((void**)&remap,  g_remap);
    cudaGetSymbolAddress((void**)&rowbase,g_rowbase);
    cudaGetSymbolAddress((void**)&rowcnt, g_rowcnt);
    cudaGetSymbolAddress((void**)&csrsrc, g_csrsrc);
    cudaGetSymbolAddress((void**)&wp1,    g_Wp1);
    cudaGetSymbolAddress((void**)&wp2,    g_Wp2);
    cudaGetSymbolAddress((void**)&pool,   g_pool);

    const int MEGA_SMEM = 512 * 64 * (int)sizeof(float);   // 128 KB dynamic
    cudaFuncSetAttribute(k_mega, cudaFuncAttributeMaxDynamicSharedMemorySize, MEGA_SMEM);

    k_packW2<<<(2 * 64 * HF + 255) / 256, 256>>>(conv1_W, conv2_W, wp1, wp2);

    // ---------- layer 0 ----------
    k_csr<<<BGR, 512>>>(src0, dst0, nullptr, NPER0, rowbase, rowcnt, csrsrc, dinv);
    k_gemm3<<<N0 / 64, 256>>>(x, wp1, bufB);
    k_mega<<<BGR, 1024, MEGA_SMEM>>>(bufB, csrsrc, rowbase, rowcnt, dinv,
                                     conv1_b, score1_W, score1_b,
                                     bn1_g, bn1_b, bn1_m, bn1_v,
                                     NPER0, K1, bufA, remap, bufC,
                                     pool + BGR * HF, 1);

    // ---------- layer 1 ----------
    k_csr<<<BGR, 512>>>(src0, dst0, remap, K1, rowbase, rowcnt, csrsrc, dinv);
    k_gemm3<<<N1 / 64, 256>>>(bufC, wp2, bufB);
    k_mega<<<BGR, 1024, MEGA_SMEM>>>(bufB, csrsrc, rowbase, rowcnt, dinv,
                                     conv2_b, score2_W, score2_b,
                                     bn2_g, bn2_b, bn2_m, bn2_v,
                                     K1, K2, bufA, remap, nullptr,
                                     pool + 2 * BGR * HF, 0);

    // ---------- readout ----------
    k_pooled<<<BGR, 512>>>(x, NPER0, pool);
    k_final<<<(BGR * DOUT + 255) / 256, 256>>>(pool,
                                               lin0_W, lin0_b, lin1_W, lin1_b, lin2_W, lin2_b,
                                               out);
}

// round 7
// speedup vs baseline: 1.1147x; 1.0176x over previous
#include <cuda_runtime.h>
#include <math.h>
#include <stdint.h>

// ---------------- problem constants ----------------
#define BGR   128          // graphs
#define NPER0 512          // nodes per graph, layer 0
#define EPG   8192         // edges per graph
#define EPGP  10240        // padded csr stride per graph (rows 4-aligned)
#define EE    (BGR*EPG)
#define N0    (BGR*NPER0)  // 65536
#define K1    410
#define K2    328
#define N1    (BGR*K1)     // 52480 (divisible by 64)
#define HF    128
#define DOUT  10
#define BN_EPS 1e-5f

typedef unsigned long long u64;

// ---------------- static device scratch ----------------
__device__ float g_bufA[(size_t)N0*HF];   // GCN agg output
__device__ float g_bufB[(size_t)N0*HF];   // X@W
__device__ float g_bufC[(size_t)N1*HF];   // hp1
__device__ float g_dinv[N0];
__device__ int   g_remap[N0];
__device__ int   g_rowbase[N0];
__device__ int   g_rowcnt[N0];
__device__ int   g_csrsrc[(size_t)BGR*EPGP];  // stores s_local<<8 (smem byte offset)
__device__ u64   g_Wp1[64*HF];
__device__ u64   g_Wp2[64*HF];
__device__ float g_pool[3*BGR*HF];

// ---------------- packed fp32x2 fma ----------------
__device__ __forceinline__ u64 ffma2(u64 a, u64 b, u64 c) {
    u64 d;
    asm("fma.rn.f32x2 %0, %1, %2, %3;" : "=l"(d) : "l"(a), "l"(b), "l"(c));
    return d;
}

// ---------------- pack both weight matrices ----------------
__global__ void k_packW2(const float* __restrict__ W1, const float* __restrict__ W2,
                         u64* __restrict__ Wp1, u64* __restrict__ Wp2) {
    int i = blockIdx.x * blockDim.x + threadIdx.x;
    const int n = 64 * HF;
    if (i >= 2 * n) return;
    const float* W = (i < n) ? W1 : W2;
    u64* Wp = (i < n) ? Wp1 : Wp2;
    int j = (i < n) ? i : i - n;
    int kp = j >> 7, c = j & 127;
    u64 lo = __float_as_uint(W[(2 * kp) * HF + c]);
    u64 hi = __float_as_uint(W[(2 * kp + 1) * HF + c]);
    Wp[j] = lo | (hi << 32);
}

// ---------------- CSR v2: one pass over edges, padded 4-aligned rows ----------
// csr values are s_local*256 (byte offset into 64-float stage rows).
__global__ void __launch_bounds__(512)
k_csr(const int* __restrict__ src, const int* __restrict__ dst,
      const int* __restrict__ remap, int nper_dst,
      int* __restrict__ row_base, int* __restrict__ row_cnt,
      int* __restrict__ csr, float* __restrict__ dinv) {
    __shared__ int cnt[512];
    __shared__ int off[512];
    __shared__ int cur[512];
    __shared__ int wsum[16];
    __shared__ int remap_s[NPER0];
    __shared__ unsigned ed[EPG];            // packed (s_local<<16)|d_local
    int g = blockIdx.x, tid = threadIdx.x;
    int lane = tid & 31, wid = tid >> 5;
    cnt[tid] = 0; cur[tid] = 0;
    if (remap) remap_s[tid] = remap[g * NPER0 + tid];
    __syncthreads();
    int ebase = g * EPG;
    int gdst = g * nper_dst;
    for (int e = tid; e < EPG; e += 512) {
        int s = src[ebase + e] - g * NPER0;
        int d = dst[ebase + e] - g * NPER0;
        unsigned pk = 0xFFFFFFFFu;
        if (remap) {
            int rs = remap_s[s], rd = remap_s[d];
            if ((rs | rd) >= 0)
                pk = ((unsigned)(rs - gdst) << 16) | (unsigned)(rd - gdst);
        } else {
            pk = ((unsigned)s << 16) | (unsigned)d;
        }
        ed[e] = pk;
        if (pk != 0xFFFFFFFFu) atomicAdd(&cnt[pk & 0xFFFFu], 1);
    }
    __syncthreads();
    int c = cnt[tid];
    int pc = (c + 3) & ~3;                  // padded to 4 for int4 loads
    int v = pc;
    #pragma unroll
    for (int d2 = 1; d2 < 32; d2 <<= 1) {
        int t = __shfl_up_sync(0xFFFFFFFFu, v, d2);
        if (lane >= d2) v += t;
    }
    if (lane == 31) wsum[wid] = v;
    __syncthreads();
    if (tid < 16) {
        int w = wsum[tid];
        #pragma unroll
        for (int d2 = 1; d2 < 16; d2 <<= 1) {
            int t = __shfl_up_sync(0xFFFFu, w, d2);
            if (tid >= d2) w += t;
        }
        wsum[tid] = w;
    }
    __syncthreads();
    int excl = v - pc + ((wid > 0) ? wsum[wid - 1] : 0);
    int ebp = g * EPGP;
    if (tid < nper_dst) {
        row_cnt[gdst + tid]  = c;
        row_base[gdst + tid] = ebp + excl;
        dinv[gdst + tid]     = rsqrtf(1.0f + (float)c);
    }
    off[tid] = excl;
    __syncthreads();
    for (int e = tid; e < EPG; e += 512) {
        unsigned pk = ed[e];
        if (pk != 0xFFFFFFFFu) {
            int d = pk & 0xFFFFu, s = pk >> 16;
            int p = atomicAdd(&cur[d], 1);
            csr[ebp + off[d] + p] = s << 8;   // byte offset into stage
        }
    }
}

// ---------------- GEMM v3: Y[nrows,128] = X @ W, packed f32x2 ----------------
__global__ void __launch_bounds__(256, 2)
k_gemm3(const float* __restrict__ X, const u64* __restrict__ Wp,
        float* __restrict__ Y) {
    __shared__ float Xs[64][HF];
    int row0 = blockIdx.x * 64;
    int tid = threadIdx.x;
    #pragma unroll
    for (int j = 0; j < 8; j++) {
        int idx = j * 256 + tid;
        int r = idx >> 5, c4 = idx & 31;
        float4 v = *(const float4*)(X + (size_t)(row0 + r) * HF + c4 * 4);
        *(float4*)(&Xs[r][c4 * 4]) = v;
    }
    __syncthreads();
    int wid = tid >> 5, lane = tid & 31;
    int r0 = wid * 8, c0 = lane * 4;
    u64 acc[8][4] = {};
    const u64* wp = Wp + c0;
    #pragma unroll 1
    for (int kp4 = 0; kp4 < 16; kp4++) {
        const u64* wb = wp + (size_t)(kp4 * 4) * HF;
        ulonglong2 wA0 = *(const ulonglong2*)(wb);
        ulonglong2 wB0 = *(const ulonglong2*)(wb + 2);
        ulonglong2 wA1 = *(const ulonglong2*)(wb + HF);
        ulonglong2 wB1 = *(const ulonglong2*)(wb + HF + 2);
        ulonglong2 wA2 = *(const ulonglong2*)(wb + 2 * HF);
        ulonglong2 wB2 = *(const ulonglong2*)(wb + 2 * HF + 2);
        ulonglong2 wA3 = *(const ulonglong2*)(wb + 3 * HF);
        ulonglong2 wB3 = *(const ulonglong2*)(wb + 3 * HF + 2);
        #pragma unroll
        for (int i = 0; i < 8; i++) {
            ulonglong2 xa = *(const ulonglong2*)(&Xs[r0 + i][kp4 * 8]);
            ulonglong2 xb = *(const ulonglong2*)(&Xs[r0 + i][kp4 * 8 + 4]);
            acc[i][0] = ffma2(xa.x, wA0.x, acc[i][0]);
            acc[i][1] = ffma2(xa.x, wA0.y, acc[i][1]);
            acc[i][2] = ffma2(xa.x, wB0.x, acc[i][2]);
            acc[i][3] = ffma2(xa.x, wB0.y, acc[i][3]);
            acc[i][0] = ffma2(xa.y, wA1.x, acc[i][0]);
            acc[i][1] = ffma2(xa.y, wA1.y, acc[i][1]);
            acc[i][2] = ffma2(xa.y, wB1.x, acc[i][2]);
            acc[i][3] = ffma2(xa.y, wB1.y, acc[i][3]);
            acc[i][0] = ffma2(xb.x, wA2.x, acc[i][0]);
            acc[i][1] = ffma2(xb.x, wA2.y, acc[i][1]);
            acc[i][2] = ffma2(xb.x, wB2.x, acc[i][2]);
            acc[i][3] = ffma2(xb.x, wB2.y, acc[i][3]);
            acc[i][0] = ffma2(xb.y, wA3.x, acc[i][0]);
            acc[i][1] = ffma2(xb.y, wA3.y, acc[i][1]);
            acc[i][2] = ffma2(xb.y, wB3.x, acc[i][2]);
            acc[i][3] = ffma2(xb.y, wB3.y, acc[i][3]);
        }
    }
    #pragma unroll
    for (int i = 0; i < 8; i++) {
        int r = row0 + r0 + i;
        float2 p0 = *(float2*)&acc[i][0];
        float2 p1 = *(float2*)&acc[i][1];
        float2 p2 = *(float2*)&acc[i][2];
        float2 p3 = *(float2*)&acc[i][3];
        float4 o = make_float4(p0.x + p0.y, p1.x + p1.y, p2.x + p2.y, p3.x + p3.y);
        *(float4*)(Y + (size_t)r * HF + c0) = o;
    }
}

// ================= MEGA v3: one CTA (1024 thr) per graph =================
__global__ void __launch_bounds__(1024, 1)
k_mega(const float* __restrict__ H,
       const int* __restrict__ csr,
       const int* __restrict__ row_base, const int* __restrict__ row_cnt,
       const float* __restrict__ dinv,
       const float* __restrict__ bias, const float* __restrict__ sW,
       const float* __restrict__ sb,
       const float* __restrict__ bg, const float* __restrict__ bb,
       const float* __restrict__ bm, const float* __restrict__ bv,
       int nper, int k,
       float* __restrict__ outAgg, int* __restrict__ remap,
       float* __restrict__ hp /*may be null*/, float* __restrict__ pooled,
       int write_remap) {
    extern __shared__ float stage[];          // nper rows x 64 floats (256 B/row)
    __shared__ float di_s[512];
    __shared__ float hs_s[512];
    __shared__ float hsdi_s[512];
    __shared__ float sc_s[512];
    __shared__ float tn_s[512];
    __shared__ int   inv_s[512];
    __shared__ int   wsum[16];
    __shared__ float bnA[HF];
    __shared__ float bnC[HF];
    __shared__ float pool_s[HF];

    int g = blockIdx.x, tid = threadIdx.x;
    int lane = tid & 31, wid = tid >> 5;
    int gbase = g * nper;

    if (tid < HF) {
        float A = bg[tid] * rsqrtf(bv[tid] + BN_EPS);
        bnA[tid] = A;
        bnC[tid] = bb[tid] - A * bm[tid];
        pool_s[tid] = 0.f;
    }
    if (tid < 512) {
        di_s[tid] = (tid < nper) ? dinv[gbase + tid] : 0.f;
        hs_s[tid] = 0.f;
    }
    __syncthreads();

    // ---- two feature-chunk passes of 64 ----
    #pragma unroll 1
    for (int cf = 0; cf < HF; cf += 64) {
        for (int i2 = tid; i2 < nper * 16; i2 += 1024) {
            int row = i2 >> 4, f4 = (i2 & 15) * 4;
            float4 v = *(const float4*)(H + (size_t)(gbase + row) * HF + cf + f4);
            float d = di_s[row];
            v.x *= d; v.y *= d; v.z *= d; v.w *= d;
            *(float4*)(&stage[row * 64 + f4]) = v;
        }
        __syncthreads();
        int fp = 2 * lane;                                // float index of lane's pair
        const char* sf = (const char*)stage + fp * 4;     // byte offset (FIXED: *4)
        float2 bp = *(const float2*)(bias + cf + fp);
        float2 wv = *(const float2*)(sW + cf + fp);
        for (int v = wid; v < nper; v += 32) {
            int base = row_base[gbase + v], cnt = row_cnt[gbase + v];
            const int* cp = csr + base;                   // 16B-aligned
            float2 self = *(const float2*)(sf + v * 256);
            float a0x = self.x, a0y = self.y, a1x = 0.f, a1y = 0.f;
            int e = 0;
            for (; e + 4 <= cnt; e += 4) {
                int4 o = *(const int4*)(cp + e);
                float2 v0 = *(const float2*)(sf + o.x);
                float2 v1 = *(const float2*)(sf + o.y);
                float2 v2 = *(const float2*)(sf + o.z);
                float2 v3 = *(const float2*)(sf + o.w);
                a0x += v0.x + v1.x; a0y += v0.y + v1.y;
                a1x += v2.x + v3.x; a1y += v2.y + v3.y;
            }
            for (; e < cnt; e++) {
                float2 v0 = *(const float2*)(sf + cp[e]);
                a0x += v0.x; a0y += v0.y;
            }
            float d = di_s[v];
            float o0 = (a0x + a1x) * d + bp.x;
            float o1 = (a0y + a1y) * d + bp.y;
            *(float2*)(outAgg + (size_t)(gbase + v) * HF + cf + fp) = make_float2(o0, o1);
            float p = o0 * wv.x + o1 * wv.y;
            #pragma unroll
            for (int off = 16; off > 0; off >>= 1) p += __shfl_down_sync(0xFFFFFFFFu, p, off);
            if (lane == 0) hs_s[v] += p;
        }
        __syncthreads();
    }

    // ---- hs*dinv table ----
    if (tid < 512) hsdi_s[tid] = hs_s[tid] * di_s[tid];
    __syncthreads();

    // ---- score aggregation (all from smem) ----
    float scv = -1e30f;
    if (tid < nper) {
        int base = row_base[gbase + tid], cnt = row_cnt[gbase + tid];
        const int* cp = csr + base;
        const char* hb = (const char*)hsdi_s;
        float acc0 = 0.f, acc1 = 0.f;
        int e = 0;
        for (; e + 4 <= cnt; e += 4) {
            int4 o = *(const int4*)(cp + e);
            acc0 += *(const float*)(hb + (o.x >> 6)) + *(const float*)(hb + (o.y >> 6));
            acc1 += *(const float*)(hb + (o.z >> 6)) + *(const float*)(hb + (o.w >> 6));
        }
        for (; e < cnt; e++)
            acc0 += *(const float*)(hb + (cp[e] >> 6));
        float di = di_s[tid];
        scv = (acc0 + acc1 + hsdi_s[tid]) * di + sb[0];
    }
    if (tid < 512) sc_s[tid] = scv;
    __syncthreads();

    // ---- exact rank (ties -> lower index), float2 reads ----
    int kept = 0;
    if (tid < nper) {
        float si = scv;
        int rank = 0;
        const float2* sc2 = (const float2*)sc_s;
        for (int j2 = 0; j2 < 256; j2++) {
            float2 pj = sc2[j2];
            rank += (pj.x > si) || (pj.x == si && (2 * j2)     < tid);
            rank += (pj.y > si) || (pj.y == si && (2 * j2 + 1) < tid);
        }
        kept = (rank < k) ? 1 : 0;
    }

    // ---- warp-shuffle scan over 512 ----
    int v = kept;
    if (tid < 512) {
        #pragma unroll
        for (int d2 = 1; d2 < 32; d2 <<= 1) {
            int t = __shfl_up_sync(0xFFFFFFFFu, v, d2);
            if (lane >= d2) v += t;
        }
        if (lane == 31) wsum[wid] = v;
    }
    __syncthreads();
    if (tid < 16) {
        int w = wsum[tid];
        #pragma unroll
        for (int d2 = 1; d2 < 16; d2 <<= 1) {
            int t = __shfl_up_sync(0xFFFFu, w, d2);
            if (tid >= d2) w += t;
        }
        wsum[tid] = w;
    }
    __syncthreads();
    if (tid < nper) {
        int incl = v + ((wid > 0) ? wsum[wid - 1] : 0);
        int pos = incl - 1;
        if (write_remap) remap[gbase + tid] = kept ? (g * k + pos) : -1;
        if (kept) {
            inv_s[pos] = tid;
            tn_s[pos]  = tanhf(scv);
        }
    }
    __syncthreads();

    // ---- copy kept rows: tanh gate + folded BN + ReLU; fused pooled sums ----
    {
        int c4 = (tid & 31) * 4;
        float A0 = bnA[c4+0], A1 = bnA[c4+1], A2 = bnA[c4+2], A3 = bnA[c4+3];
        float C0 = bnC[c4+0], C1 = bnC[c4+1], C2 = bnC[c4+2], C3 = bnC[c4+3];
        float s0 = 0.f, s1 = 0.f, s2 = 0.f, s3 = 0.f;
        const float* abase = outAgg + (size_t)gbase * HF;
        float* obase = hp ? (hp + (size_t)g * k * HF) : (float*)0;
        for (int rn = tid >> 5; rn < k; rn += 32) {
            int ro = inv_s[rn];
            float t = tn_s[rn];
            float4 h = *(const float4*)(abase + (size_t)ro * HF + c4);
            float4 o;
            o.x = fmaxf(A0 * (h.x * t) + C0, 0.f);
            o.y = fmaxf(A1 * (h.y * t) + C1, 0.f);
            o.z = fmaxf(A2 * (h.z * t) + C2, 0.f);
            o.w = fmaxf(A3 * (h.w * t) + C3, 0.f);
            if (obase) *(float4*)(obase + (size_t)rn * HF + c4) = o;
            s0 += o.x; s1 += o.y; s2 += o.z; s3 += o.w;
        }
        atomicAdd(&pool_s[c4+0], s0);
        atomicAdd(&pool_s[c4+1], s1);
        atomicAdd(&pool_s[c4+2], s2);
        atomicAdd(&pool_s[c4+3], s3);
    }
    __syncthreads();
    if (tid < HF) pooled[g * HF + tid] = pool_s[tid];
}

// ---------------- per-graph feature sum of x (layer 0 pooled) ----------------
__global__ void k_pooled(const float* __restrict__ X, int nper, float* __restrict__ P) {
    __shared__ float red[4][HF];
    int g = blockIdx.x;
    int f = threadIdx.x & 127, q = threadIdx.x >> 7;
    const float* base = X + (size_t)g * nper * HF + f;
    float acc = 0.f;
    for (int r = q; r < nper; r += 4) acc += base[(size_t)r * HF];
    red[q][f] = acc;
    __syncthreads();
    if (q == 0)
        P[g * HF + f] = red[0][f] + red[1][f] + red[2][f] + red[3][f];
}

// ---------------- readout ----------------
__global__ void k_final(const float* __restrict__ P,
                        const float* __restrict__ W0, const float* __restrict__ b0,
                        const float* __restrict__ W1, const float* __restrict__ b1,
                        const float* __restrict__ W2, const float* __restrict__ b2,
                        float* __restrict__ out) {
    int idx = blockIdx.x * blockDim.x + threadIdx.x;
    if (idx >= BGR * DOUT) return;
    int b = idx / DOUT, o = idx % DOUT;
    float acc = b0[o] + b1[o] + b2[o];
    const float* p0 = P + b * HF;
    const float* p1 = P + (BGR + b) * HF;
    const float* p2 = P + (2 * BGR + b) * HF;
    const float* w0 = W0 + o * HF;
    const float* w1 = W1 + o * HF;
    const float* w2 = W2 + o * HF;
    #pragma unroll 4
    for (int f = 0; f < HF; f++)
        acc += p0[f] * w0[f] + p1[f] * w1[f] + p2[f] * w2[f];
    out[idx] = acc;
}

// ---------------- host launch ----------------
extern "C" void kernel_launch(void* const* d_in, const int* in_sizes, int n_in,
                              void* d_out, int out_size) {
    const float* x        = (const float*)d_in[0];
    const int*   ei       = (const int*)  d_in[1];
    const float* conv1_W  = (const float*)d_in[2];
    const float* conv1_b  = (const float*)d_in[3];
    const float* conv2_W  = (const float*)d_in[4];
    const float* conv2_b  = (const float*)d_in[5];
    const float* score1_W = (const float*)d_in[6];
    const float* score1_b = (const float*)d_in[7];
    const float* score2_W = (const float*)d_in[8];
    const float* score2_b = (const float*)d_in[9];
    const float* bn1_g    = (const float*)d_in[10];
    const float* bn1_b    = (const float*)d_in[11];
    const float* bn1_m    = (const float*)d_in[12];
    const float* bn1_v    = (const float*)d_in[13];
    const float* bn2_g    = (const float*)d_in[14];
    const float* bn2_b    = (const float*)d_in[15];
    const float* bn2_m    = (const float*)d_in[16];
    const float* bn2_v    = (const float*)d_in[17];
    const float* lin0_W   = (const float*)d_in[18];
    const float* lin0_b   = (const float*)d_in[19];
    const float* lin1_W   = (const float*)d_in[20];
    const float* lin1_b   = (const float*)d_in[21];
    const float* lin2_W   = (const float*)d_in[22];
    const float* lin2_b   = (const float*)d_in[23];
    float* out = (float*)d_out;

    const int* src0 = ei;
    const int* dst0 = ei + EE;

    float *bufA, *bufB, *bufC, *dinv, *pool;
    int *remap, *rowbase, *rowcnt, *csrsrc;
    u64 *wp1, *wp2;
    cudaGetSymbolAddress((void**)&bufA,   g_bufA);
    cudaGetSymbolAddress((void**)&bufB,   g_bufB);
    cudaGetSymbolAddress((void**)&bufC,   g_bufC);
    cudaGetSymbolAddress((void**)&dinv,   g_dinv);
    cudaGetSymbolAddress((void**)&remap,  g_remap);
    cudaGetSymbolAddress((void**)&rowbase,g_rowbase);
    cudaGetSymbolAddress((void**)&rowcnt, g_rowcnt);
    cudaGetSymbolAddress((void**)&csrsrc, g_csrsrc);
    cudaGetSymbolAddress((void**)&wp1,    g_Wp1);
    cudaGetSymbolAddress((void**)&wp2,    g_Wp2);
    cudaGetSymbolAddress((void**)&pool,   g_pool);

    const int MEGA_SMEM = 512 * 64 * (int)sizeof(float);   // 128 KB dynamic
    cudaFuncSetAttribute(k_mega, cudaFuncAttributeMaxDynamicSharedMemorySize, MEGA_SMEM);

    k_packW2<<<(2 * 64 * HF + 255) / 256, 256>>>(conv1_W, conv2_W, wp1, wp2);

    // ---------- layer 0 ----------
    k_csr<<<BGR, 512>>>(src0, dst0, nullptr, NPER0, rowbase, rowcnt, csrsrc, dinv);
    k_gemm3<<<N0 / 64, 256>>>(x, wp1, bufB);
    k_mega<<<BGR, 1024, MEGA_SMEM>>>(bufB, csrsrc, rowbase, rowcnt, dinv,
                                     conv1_b, score1_W, score1_b,
                                     bn1_g, bn1_b, bn1_m, bn1_v,
                                     NPER0, K1, bufA, remap, bufC,
                                     pool + BGR * HF, 1);

    // ---------- layer 1 ----------
    k_csr<<<BGR, 512>>>(src0, dst0, remap, K1, rowbase, rowcnt, csrsrc, dinv);
    k_gemm3<<<N1 / 64, 256>>>(bufC, wp2, bufB);
    k_mega<<<BGR, 1024, MEGA_SMEM>>>(bufB, csrsrc, rowbase, rowcnt, dinv,
                                     conv2_b, score2_W, score2_b,
                                     bn2_g, bn2_b, bn2_m, bn2_v,
                                     K1, K2, bufA, remap, nullptr,
                                     pool + 2 * BGR * HF, 0);

    // ---------- readout ----------
    k_pooled<<<BGR, 512>>>(x, NPER0, pool);
    k_final<<<(BGR * DOUT + 255) / 256, 256>>>(pool,
                                               lin0_W, lin0_b, lin1_W, lin1_b, lin2_W, lin2_b,
                                               out);
}